// round 1
// baseline (speedup 1.0000x reference)
#include <cuda_runtime.h>
#include <math.h>

#define Bn 32
#define Cn 224
#define Tn 2048
#define TT 32   // t-tile per block (and threads per block) for stage-1 kernel

// Scratch: I = x - relu(x - x_mean), 32*224*2048 floats = 58.7 MB
__device__ float g_I[(size_t)Bn * Cn * Tn];

// ---------------------------------------------------------------------------
// Kernel 1: per (b, t-tile):
//   - load x[b, 0:224, t0:t0+TT] into SMEM
//   - per t: w = clip(5.2 + dot(x[b,:,t], lw)*9.6, 0.4, 10)
//   - kern[k] = exp(-0.5*((k-6)/w)^2);  norm = sum_{130} exp(-0.5*(r_all/w)^2)
//     computed via the geometric-ratio recurrence (2 exps instead of 130)
//   - x_mean over channels (13-tap), I = x - relu(x - x_mean), store to g_I
// Reference op order preserved (no FMA contraction) for numerical fidelity.
// ---------------------------------------------------------------------------
__global__ void __launch_bounds__(TT) agss_stage1(const float* __restrict__ x,
                                                  const float* __restrict__ lw) {
    __shared__ float xs[Cn * TT];   // x slab [c][t]
    __shared__ float lws[Cn];

    const int tid = threadIdx.x;          // owns column t = t0 + tid
    const int b   = blockIdx.y;
    const int t0  = blockIdx.x * TT;

    const float* xb = x + ((size_t)b * Cn) * Tn + t0;

    for (int c = tid; c < Cn; c += TT) lws[c] = lw[c];
    #pragma unroll 4
    for (int c = 0; c < Cn; c++) xs[c * TT + tid] = xb[(size_t)c * Tn + tid];
    __syncthreads();

    // --- dot over channels (Kahan-compensated fp32: ~double accuracy) ---
    float s = 0.0f, comp = 0.0f;
    #pragma unroll 4
    for (int c = 0; c < Cn; c++) {
        float prod = __fmul_rn(xs[c * TT + tid], lws[c]);
        float y  = __fsub_rn(prod, comp);
        float t2 = __fadd_rn(s, y);
        comp = __fsub_rn(__fsub_rn(t2, s), y);
        s = t2;
    }
    float w = __fadd_rn(5.2f, __fmul_rn(s, 9.6f));
    w = fminf(fmaxf(w, 0.4f), 10.0f);

    // --- 13-tap kernel ---
    float kern[13];
    #pragma unroll
    for (int k = 0; k < 13; k++) {
        float r = (float)(k - 6);
        float q = r / w;
        kern[k] = expf(__fmul_rn(-0.5f, __fmul_rn(q, q)));
    }

    // --- normalizer: 2 * sum_{m=0}^{64} exp(-a*(m+0.5)^2), a = 0.5*(d/w)^2 ---
    {
        float dd  = 0.93023255813953487f;        // 120/129
        float q0  = dd / w;
        float a   = 0.5f * q0 * q0;
        float rho  = expf(-2.0f * a);            // ratio generator
        float term = expf(-0.25f * a);           // t_0
        float ssum = term;
        float qq   = rho;
        #pragma unroll 8
        for (int m = 0; m < 64; m++) {
            term = __fmul_rn(term, qq);          // t_{m+1} = t_m * rho^{m+1}
            ssum = __fadd_rn(ssum, term);
            qq   = __fmul_rn(qq, rho);
        }
        float fn = __fmul_rn(2.0f, ssum);
        #pragma unroll
        for (int k = 0; k < 13; k++) kern[k] = __fdiv_rn(kern[k], fn);
    }

    // --- channel conv (13 taps) with register sliding window, direct store ---
    // invariant: win[(c+i) % 13] == x[c-6+i]   (zero outside [0, Cn))
    float win[13];
    #pragma unroll
    for (int i = 0; i < 13; i++) {
        int c = i - 6;
        win[i] = (c >= 0) ? xs[c * TT + tid] : 0.0f;
    }

    float* Ib = g_I + ((size_t)b * Cn) * Tn + t0 + tid;

    // 234 = 18*13 trips so all %13 indices are compile-time constants
    for (int base = 0; base < 234; base += 13) {
        #pragma unroll
        for (int k = 0; k < 13; k++) {
            const int c = base + k;
            if (c < Cn) {
                // reference order: ((t0 + t1) + t2) + ... , no fma
                float acc = __fmul_rn(win[(k + 0) % 13], kern[0]);
                #pragma unroll
                for (int j = 1; j < 13; j++)
                    acc = __fadd_rn(acc, __fmul_rn(win[(k + j) % 13], kern[j]));
                float xc = win[(k + 6) % 13];
                float df = __fsub_rn(xc, acc);
                float rl = fmaxf(df, 0.0f);
                Ib[(size_t)c * Tn] = __fsub_rn(xc, rl);   // I = x - relu(x - xm)
            }
            int cn = base + k + 7;
            win[k] = (cn < Cn) ? xs[cn * TT + tid] : 0.0f;   // slot k == c % 13
        }
    }
}

// ---------------------------------------------------------------------------
// Kernel 2: LIF scan over t for each (b,c) sequence.
//   reset_t = (mem_{t-1} > 1) == spk_{t-1}  -> reuse previous spike
//   mem = (0.95*mem + I) - reset            (exact reference op order)
//   spk = (mem - 1 > 0) <=> (mem > 1)       (exact equivalence in IEEE)
// One warp per block (224 blocks) to spread chains across all SMs.
// ---------------------------------------------------------------------------
__global__ void __launch_bounds__(32) agss_stage2(float* __restrict__ out) {
    const int seq = blockIdx.x * 32 + threadIdx.x;    // 0 .. 7167 = b*224 + c
    const float* Ip = g_I + (size_t)seq * Tn;
    float* op = out + (size_t)seq * Tn;

    float mem = 0.0f;
    float sp  = 0.0f;   // spk_{t-1} == reset_t

    #pragma unroll 2
    for (int t = 0; t < Tn; t += 4) {
        float4 v = *(const float4*)(Ip + t);
        float4 o;

        mem = __fsub_rn(__fadd_rn(__fmul_rn(0.95f, mem), v.x), sp);
        sp = (mem > 1.0f) ? 1.0f : 0.0f;  o.x = sp;
        mem = __fsub_rn(__fadd_rn(__fmul_rn(0.95f, mem), v.y), sp);
        sp = (mem > 1.0f) ? 1.0f : 0.0f;  o.y = sp;
        mem = __fsub_rn(__fadd_rn(__fmul_rn(0.95f, mem), v.z), sp);
        sp = (mem > 1.0f) ? 1.0f : 0.0f;  o.z = sp;
        mem = __fsub_rn(__fadd_rn(__fmul_rn(0.95f, mem), v.w), sp);
        sp = (mem > 1.0f) ? 1.0f : 0.0f;  o.w = sp;

        *(float4*)(op + t) = o;
    }
}

// ---------------------------------------------------------------------------
extern "C" void kernel_launch(void* const* d_in, const int* in_sizes, int n_in,
                              void* d_out, int out_size) {
    const float* inp = (const float*)d_in[0];   // (32,1,224,2048) f32
    const float* lw  = (const float*)d_in[1];   // (1,224) f32
    float* out = (float*)d_out;                 // (32,1,224,2048) f32

    dim3 g1(Tn / TT, Bn);
    agss_stage1<<<g1, TT>>>(inp, lw);
    agss_stage2<<<(Bn * Cn) / 32, 32>>>(out);
}

// round 2
// speedup vs baseline: 2.4611x; 2.4611x over previous
#include <cuda_runtime.h>
#include <math.h>

#define Bn 32
#define Cn 224
#define Tn 2048
#define TT 32            // t-columns per stage-1 block
#define NW 4             // warps per stage-1 block
#define CW 56            // channels per warp (4*56 = 224)
#define BC (Bn * Cn)     // 7168 sequences
#define PF 64            // stage-2 register prefetch depth

// Transposed intermediate: I_T[t][seq], seq = b*224 + c.  58.7 MB (fits L2).
__device__ float g_IT[(size_t)Tn * BC];

// ---------------------------------------------------------------------------
// Stage 1: per (b, 32-t-tile), 128 threads (4 warps x 56 channels each).
//   - cooperative load of x slab [224][32] into smem
//   - per-warp exact Kahan partial dot -> ordered 4-way reduce -> w (clipped)
//   - 13-tap kernel + geometric-recurrence normalizer (2 exps, not 130)
//   - per-warp register sliding-window channel conv (FFMA), I into smem
//   - smem transpose -> coalesced stores to g_IT[t][seq]
// ---------------------------------------------------------------------------
__global__ void __launch_bounds__(128) agss_stage1(const float* __restrict__ x,
                                                   const float* __restrict__ lw) {
    __shared__ float xs[Cn * TT];           // [c][t], rows of 32 floats
    __shared__ float Is[Cn * (TT + 1)];     // [c][t] padded (stride 33)
    __shared__ float lws[Cn];
    __shared__ float pdot[NW][TT];

    const int tid  = threadIdx.x;
    const int lane = tid & 31;              // owns t-column t0 + lane
    const int wid  = tid >> 5;
    const int b    = blockIdx.y;
    const int t0   = blockIdx.x * TT;

    const float* xb = x + ((size_t)b * Cn) * Tn + t0;

    if (tid < Cn) lws[tid] = lw[tid];
    if (tid + 128 < Cn) lws[tid + 128] = lw[tid + 128];

    #pragma unroll
    for (int i = tid; i < Cn * TT; i += 128) {
        int c = i >> 5, tt = i & 31;
        xs[i] = xb[(size_t)c * Tn + tt];
    }
    __syncthreads();

    // --- per-warp Kahan partial dot over channels [c0, c0+56) ---
    const int c0 = wid * CW;
    {
        float s = 0.0f, comp = 0.0f;
        #pragma unroll
        for (int j = 0; j < CW; j++) {
            int c = c0 + j;
            float prod = __fmul_rn(xs[c * TT + lane], lws[c]);
            float y  = __fsub_rn(prod, comp);
            float t2 = __fadd_rn(s, y);
            comp = __fsub_rn(__fsub_rn(t2, s), y);
            s = t2;
        }
        pdot[wid][lane] = __fadd_rn(s, comp);
    }
    __syncthreads();

    // ordered reduce of the 4 (near-exact) partials
    float s = __fadd_rn(__fadd_rn(__fadd_rn(pdot[0][lane], pdot[1][lane]),
                                  pdot[2][lane]), pdot[3][lane]);
    float w = __fadd_rn(5.2f, __fmul_rn(s, 9.6f));
    w = fminf(fmaxf(w, 0.4f), 10.0f);

    // --- 13-tap kernel ---
    float kern[13];
    #pragma unroll
    for (int k = 0; k < 13; k++) {
        float r = (float)(k - 6);
        float q = r / w;
        kern[k] = expf(__fmul_rn(-0.5f, __fmul_rn(q, q)));
    }

    // --- normalizer: 2 * sum_{m=0}^{64} exp(-a*(m+0.5)^2) via geometric ratios ---
    {
        float dd   = 0.93023255813953487f;   // 120/129
        float q0   = dd / w;
        float a    = 0.5f * q0 * q0;
        float rho  = expf(-2.0f * a);
        float term = expf(-0.25f * a);
        float ssum = term;
        float qq   = rho;
        #pragma unroll 8
        for (int m = 0; m < 64; m++) {
            term = __fmul_rn(term, qq);
            ssum = __fadd_rn(ssum, term);
            qq   = __fmul_rn(qq, rho);
        }
        float fn = __fmul_rn(2.0f, ssum);
        #pragma unroll
        for (int k = 0; k < 13; k++) kern[k] = __fdiv_rn(kern[k], fn);
    }

    // --- per-warp channel conv with register sliding window ---
    // invariant at local step j: win[(j+i)%13] == x[c0 + j - 6 + i], zero OOB
    float win[13];
    #pragma unroll
    for (int i = 0; i < 13; i++) {
        int c = c0 - 6 + i;
        win[i] = (c >= 0 && c < Cn) ? xs[c * TT + lane] : 0.0f;
    }

    #pragma unroll
    for (int j = 0; j < CW; j++) {
        float acc = __fmul_rn(win[j % 13], kern[0]);
        #pragma unroll
        for (int i = 1; i < 13; i++)
            acc = fmaf(win[(j + i) % 13], kern[i], acc);
        float xc = win[(j + 6) % 13];
        float df = __fsub_rn(xc, acc);
        float rl = fmaxf(df, 0.0f);
        Is[(c0 + j) * (TT + 1) + lane] = __fsub_rn(xc, rl);
        int cn = c0 + j + 7;
        win[j % 13] = (cn < Cn) ? xs[cn * TT + lane] : 0.0f;
    }
    __syncthreads();

    // --- transposed, coalesced store: g_IT[(t0+row)*7168 + b*224 + c] ---
    float* It = g_IT + (size_t)t0 * BC + b * Cn;
    #pragma unroll
    for (int row = 0; row < TT; row++) {
        #pragma unroll
        for (int c = tid; c < Cn; c += 128)
            It[(size_t)row * BC + c] = Is[c * (TT + 1) + row];
    }
}

// ---------------------------------------------------------------------------
// Stage 2: LIF scan, one thread per sequence (coalesced reads of g_IT[t][seq]).
// 64-deep register prefetch pipeline hides L2/DRAM latency; the 12-cycle
// FMUL->FADD->FSUB recurrence becomes the bound. Exact reference op order.
// ---------------------------------------------------------------------------
__global__ void __launch_bounds__(32) agss_stage2(float* __restrict__ out) {
    const int seq = blockIdx.x * 32 + threadIdx.x;      // b*224 + c
    const float* It = g_IT + seq;
    float* op = out + (size_t)seq * Tn;

    float buf[PF];
    #pragma unroll
    for (int i = 0; i < PF; i++) buf[i] = It[(size_t)i * BC];

    float mem = 0.0f, sp = 0.0f;
    float ob[4];

    for (int t0 = 0; t0 < Tn; t0 += PF) {
        #pragma unroll
        for (int i = 0; i < PF; i++) {
            float v = buf[i];
            int tn = t0 + PF + i;
            if (tn < Tn) buf[i] = It[(size_t)tn * BC];   // prefetch 64 ahead
            mem = __fsub_rn(__fadd_rn(__fmul_rn(0.95f, mem), v), sp);
            sp = (mem > 1.0f) ? 1.0f : 0.0f;
            ob[i & 3] = sp;
            if ((i & 3) == 3)
                *(float4*)(op + t0 + i - 3) = make_float4(ob[0], ob[1], ob[2], ob[3]);
        }
    }
}

// ---------------------------------------------------------------------------
extern "C" void kernel_launch(void* const* d_in, const int* in_sizes, int n_in,
                              void* d_out, int out_size) {
    const float* inp = (const float*)d_in[0];   // (32,1,224,2048) f32
    const float* lw  = (const float*)d_in[1];   // (1,224) f32
    float* out = (float*)d_out;                 // (32,1,224,2048) f32

    dim3 g1(Tn / TT, Bn);
    agss_stage1<<<g1, 128>>>(inp, lw);
    agss_stage2<<<BC / 32, 32>>>(out);
}

// round 3
// speedup vs baseline: 2.5207x; 1.0242x over previous
#include <cuda_runtime.h>
#include <math.h>

#define Bn 32
#define Cn 224
#define Tn 2048
#define TT 64            // t-columns per stage-1 block (2 per thread, packed)
#define NW1 8            // warps per stage-1 block
#define CW 28            // channels per warp (8*28 = 224)
#define BC (Bn * Cn)     // 7168 sequences
#define PF 64            // stage-2 register prefetch depth

// Transposed intermediate I_T[t][seq], padded by PF rows for branch-free prefetch.
__device__ float g_IT[(size_t)(Tn + PF) * BC];

// ---- packed f32x2 helpers (bit-identical per-lane rounding) --------------
typedef unsigned long long ull;
__device__ __forceinline__ ull vpack(float lo, float hi) {
    ull r; asm("mov.b64 %0, {%1, %2};" : "=l"(r) : "f"(lo), "f"(hi)); return r;
}
__device__ __forceinline__ void vunpack(float& lo, float& hi, ull v) {
    asm("mov.b64 {%0, %1}, %2;" : "=f"(lo), "=f"(hi) : "l"(v));
}
__device__ __forceinline__ ull vmul(ull a, ull b) {
    ull d; asm("mul.rn.f32x2 %0, %1, %2;" : "=l"(d) : "l"(a), "l"(b)); return d;
}
__device__ __forceinline__ ull vadd(ull a, ull b) {
    ull d; asm("add.rn.f32x2 %0, %1, %2;" : "=l"(d) : "l"(a), "l"(b)); return d;
}
__device__ __forceinline__ ull vfma(ull a, ull b, ull c) {
    ull d; asm("fma.rn.f32x2 %0, %1, %2, %3;" : "=l"(d) : "l"(a), "l"(b), "l"(c)); return d;
}

// ---------------------------------------------------------------------------
// Stage 1: per (b, 64-t-tile), 256 threads. Thread (warp w, lane l) owns the
// two t-columns (2l, 2l+1) of its warp's 28 channels [28w, 28w+28).
//   1. coop load x slab [224][64] -> xs (stride-66 rows)
//   2. per-thread Kahan partial dots (scalar, 2 cols) -> pdot
//      + pre-read conv window head halo and tail halo into registers
//   3. threads 0..63: per-column w, 13-tap kern, geometric-recurrence norm
//      (2 exps instead of 130), normalized kern -> smem (computed ONCE)
//   4. per-warp sliding-window conv in packed f32x2 (FFMA2), I overwrites xs
//   5. transposed coalesced store -> g_IT[t][seq]
// ---------------------------------------------------------------------------
__global__ void __launch_bounds__(256) agss_stage1(const float* __restrict__ x,
                                                   const float* __restrict__ lw) {
    __shared__ float xs[Cn * 66];              // [c][t] rows, stride 66
    __shared__ float lws[Cn];
    __shared__ ull   pdot[NW1][32];            // packed per (warp, lane)
    __shared__ float kern_s[13 * TT];          // normalized kern per column

    const int tid  = threadIdx.x;
    const int lane = tid & 31;
    const int wid  = tid >> 5;
    const int b    = blockIdx.y;
    const int t0   = blockIdx.x * TT;
    const int cw0  = wid * CW;

    const float* xb = x + ((size_t)b * Cn) * Tn + t0;

    if (tid < Cn) lws[tid] = lw[tid];
    #pragma unroll 4
    for (int i = tid; i < Cn * TT; i += 256) {
        int c = i >> 6, t = i & 63;
        xs[c * 66 + t] = xb[(size_t)c * Tn + t];
    }
    __syncthreads();

    const float* xcol = xs + 2 * lane;         // this thread's column pair

    // --- Kahan partial dot over own 28 channels, both columns ---
    {
        float s0 = 0.f, k0 = 0.f, s1 = 0.f, k1 = 0.f;
        #pragma unroll
        for (int j = 0; j < CW; j++) {
            float x0, x1; vunpack(x0, x1, *(const ull*)(xcol + (cw0 + j) * 66));
            float lv = lws[cw0 + j];
            float p0 = __fmul_rn(x0, lv), p1 = __fmul_rn(x1, lv);
            float y0 = __fsub_rn(p0, k0), t2 = __fadd_rn(s0, y0);
            k0 = __fsub_rn(__fsub_rn(t2, s0), y0); s0 = t2;
            float y1 = __fsub_rn(p1, k1), t3 = __fadd_rn(s1, y1);
            k1 = __fsub_rn(__fsub_rn(t3, s1), y1); s1 = t3;
        }
        pdot[wid][lane] = vpack(__fadd_rn(s0, k0), __fadd_rn(s1, k1));
    }

    // --- pre-read conv halos BEFORE xs is overwritten by neighbor warps ---
    ull win[13], hal[6];
    #pragma unroll
    for (int i = 0; i < 13; i++) {
        int c = cw0 - 6 + i;
        win[i] = (c >= 0 && c < Cn) ? *(const ull*)(xcol + c * 66) : 0ull;
    }
    #pragma unroll
    for (int i = 0; i < 6; i++) {
        int c = cw0 + CW + i;
        hal[i] = (c < Cn) ? *(const ull*)(xcol + c * 66) : 0ull;
    }
    __syncthreads();

    // --- per-column sigma -> normalized 13-tap kernel (once per column) ---
    if (tid < TT) {
        float s = 0.f;
        #pragma unroll
        for (int w = 0; w < NW1; w++) {
            float lo, hi; vunpack(lo, hi, pdot[w][tid >> 1]);
            s = __fadd_rn(s, (tid & 1) ? hi : lo);
        }
        float w = __fadd_rn(5.2f, __fmul_rn(s, 9.6f));
        w = fminf(fmaxf(w, 0.4f), 10.0f);
        float invw = __fdiv_rn(1.0f, w);

        float kern[13];
        #pragma unroll
        for (int k = 0; k < 13; k++) {
            float q = __fmul_rn((float)(k - 6), invw);
            kern[k] = expf(__fmul_rn(-0.5f, __fmul_rn(q, q)));
        }
        // norm = 2 * sum_{m=0}^{64} exp(-a*(m+0.5)^2), geometric-ratio recurrence
        float q0 = __fmul_rn(0.93023255813953487f, invw);   // (120/129)/w
        float a  = __fmul_rn(0.5f, __fmul_rn(q0, q0));
        float rho  = expf(__fmul_rn(-2.0f, a));
        float term = expf(__fmul_rn(-0.25f, a));
        float ssum = term, qq = rho;
        #pragma unroll 8
        for (int m = 0; m < 64; m++) {
            term = __fmul_rn(term, qq);
            ssum = __fadd_rn(ssum, term);
            qq   = __fmul_rn(qq, rho);
        }
        float invn = __fdiv_rn(1.0f, __fmul_rn(2.0f, ssum));
        #pragma unroll
        for (int k = 0; k < 13; k++)
            kern_s[k * TT + tid] = __fmul_rn(kern[k], invn);
    }
    __syncthreads();

    // --- packed conv (FFMA2), overwrite xs with I = x - relu(x - x_mean) ---
    ull kk[13];
    #pragma unroll
    for (int k = 0; k < 13; k++)
        kk[k] = *(const ull*)(kern_s + k * TT + 2 * lane);

    #pragma unroll
    for (int j = 0; j < CW; j++) {
        ull acc = vmul(win[j % 13], kk[0]);
        #pragma unroll
        for (int i = 1; i < 13; i++)
            acc = vfma(win[(j + i) % 13], kk[i], acc);
        float a0, a1, x0, x1;
        vunpack(a0, a1, acc);
        vunpack(x0, x1, win[(j + 6) % 13]);
        // exact reference sequence: I = x - max(x - xm, 0)
        float i0 = __fsub_rn(x0, fmaxf(__fsub_rn(x0, a0), 0.0f));
        float i1 = __fsub_rn(x1, fmaxf(__fsub_rn(x1, a1), 0.0f));
        *(float2*)(xs + (cw0 + j) * 66 + 2 * lane) = make_float2(i0, i1);
        if (j < 21)       win[j % 13] = *(const ull*)(xcol + (cw0 + j + 7) * 66);
        else if (j < 27)  win[j % 13] = hal[j - 21];
    }
    __syncthreads();

    // --- transposed coalesced store: g_IT[(t0+r)*BC + b*224 + c] ---
    float* It = g_IT + (size_t)t0 * BC + b * Cn;
    if (tid < Cn) {
        #pragma unroll 4
        for (int r = 0; r < TT; r++)
            It[(size_t)r * BC + tid] = xs[tid * 66 + r];
    }
}

// ---------------------------------------------------------------------------
// Stage 2: LIF scan, one thread per (b,c) sequence, coalesced g_IT reads.
// Branch-free 64-deep register prefetch (immediate-offset loads into padding),
// exact reference op order, smem-transposed coalesced float4 output.
// ---------------------------------------------------------------------------
__global__ void __launch_bounds__(32) agss_stage2(float* __restrict__ out) {
    __shared__ float tile[32][33];

    const int lane = threadIdx.x;
    const int seq0 = blockIdx.x * 32;
    const float* base = g_IT + seq0 + lane;
    float* ob = out + (size_t)seq0 * Tn;

    float buf[PF];
    #pragma unroll
    for (int i = 0; i < PF; i++) buf[i] = base[(size_t)i * BC];

    float mem = 0.0f, sp = 0.0f;

    for (int t0 = 0; t0 < Tn; t0 += PF) {
        const float* pre = base + (size_t)(t0 + PF) * BC;
        #pragma unroll
        for (int i = 0; i < PF; i++) {
            float v = buf[i];
            buf[i] = pre[(size_t)i * BC];           // always in-bounds (padded)
            float nm = __fmul_rn(0.95f, mem);
            mem = __fsub_rn(__fadd_rn(nm, v), sp);
            sp  = (mem > 1.0f) ? 1.0f : 0.0f;
            tile[lane][i & 31] = sp;
            if ((i & 31) == 31) {
                __syncwarp();
                const int tc = t0 + i - 31;
                const int r0 = lane >> 3;
                const int cc = (lane & 7) * 4;
                #pragma unroll
                for (int g = 0; g < 8; g++) {
                    int row = g * 4 + r0;
                    float4 o = make_float4(tile[row][cc],     tile[row][cc + 1],
                                           tile[row][cc + 2], tile[row][cc + 3]);
                    *(float4*)(ob + (size_t)row * Tn + tc + cc) = o;
                }
                __syncwarp();
            }
        }
    }
}

// ---------------------------------------------------------------------------
extern "C" void kernel_launch(void* const* d_in, const int* in_sizes, int n_in,
                              void* d_out, int out_size) {
    const float* inp = (const float*)d_in[0];   // (32,1,224,2048) f32
    const float* lw  = (const float*)d_in[1];   // (1,224) f32
    float* out = (float*)d_out;                 // (32,1,224,2048) f32

    dim3 g1(Tn / TT, Bn);
    agss_stage1<<<g1, 256>>>(inp, lw);
    agss_stage2<<<BC / 32, 32>>>(out);
}

// round 4
// speedup vs baseline: 2.5684x; 1.0189x over previous
#include <cuda_runtime.h>
#include <math.h>

#define Bn 32
#define Cn 224
#define Tn 2048
#define TT 64            // t-columns per stage-1 block (2 per thread, packed)
#define NW1 8            // warps per stage-1 block
#define CW 28            // channels per warp (8*28 = 224)
#define BC (Bn * Cn)     // 7168 sequences
#define PF 64            // stage-2 register prefetch depth (== chunk size)

// Transposed intermediate I_T[t][seq], padded by PF rows for branch-free prefetch.
__device__ float g_IT[(size_t)(Tn + PF) * BC];

// ---- packed f32x2 helpers (bit-identical per-lane rounding) --------------
typedef unsigned long long ull;
__device__ __forceinline__ ull vpack(float lo, float hi) {
    ull r; asm("mov.b64 %0, {%1, %2};" : "=l"(r) : "f"(lo), "f"(hi)); return r;
}
__device__ __forceinline__ void vunpack(float& lo, float& hi, ull v) {
    asm("mov.b64 {%0, %1}, %2;" : "=f"(lo), "=f"(hi) : "l"(v));
}
__device__ __forceinline__ ull vmul(ull a, ull b) {
    ull d; asm("mul.rn.f32x2 %0, %1, %2;" : "=l"(d) : "l"(a), "l"(b)); return d;
}
__device__ __forceinline__ ull vfma(ull a, ull b, ull c) {
    ull d; asm("fma.rn.f32x2 %0, %1, %2, %3;" : "=l"(d) : "l"(a), "l"(b), "l"(c)); return d;
}

// ---------------------------------------------------------------------------
// Stage 1: per (b, 64-t-tile), 256 threads (8 warps x 28 channels, 2 t-cols
// per thread, packed f32x2 conv). Vectorized 128-bit loads and stores.
// ---------------------------------------------------------------------------
__global__ void __launch_bounds__(256) agss_stage1(const float* __restrict__ x,
                                                   const float* __restrict__ lw) {
    __shared__ __align__(16) float xs[Cn * 68];       // [c][t] rows, stride 68
    __shared__ float lws[Cn];
    __shared__ ull   pdot[NW1][32];
    __shared__ __align__(16) float kern_s[13 * TT];

    const int tid  = threadIdx.x;
    const int lane = tid & 31;
    const int wid  = tid >> 5;
    const int b    = blockIdx.y;
    const int t0   = blockIdx.x * TT;
    const int cw0  = wid * CW;

    const float* xb = x + ((size_t)b * Cn) * Tn + t0;

    if (tid < Cn) lws[tid] = lw[tid];

    // vectorized slab load: 224 channels x 16 float4
    #pragma unroll
    for (int i = tid; i < Cn * 16; i += 256) {
        int c = i >> 4, j = i & 15;
        *(float4*)(xs + c * 68 + 4 * j) =
            *(const float4*)(xb + (size_t)c * Tn + 4 * j);
    }
    __syncthreads();

    const float* xcol = xs + 2 * lane;

    // --- Kahan partial dot over own 28 channels, both columns ---
    {
        float s0 = 0.f, k0 = 0.f, s1 = 0.f, k1 = 0.f;
        #pragma unroll
        for (int j = 0; j < CW; j++) {
            float x0, x1; vunpack(x0, x1, *(const ull*)(xcol + (cw0 + j) * 68));
            float lv = lws[cw0 + j];
            float p0 = __fmul_rn(x0, lv), p1 = __fmul_rn(x1, lv);
            float y0 = __fsub_rn(p0, k0), t2 = __fadd_rn(s0, y0);
            k0 = __fsub_rn(__fsub_rn(t2, s0), y0); s0 = t2;
            float y1 = __fsub_rn(p1, k1), t3 = __fadd_rn(s1, y1);
            k1 = __fsub_rn(__fsub_rn(t3, s1), y1); s1 = t3;
        }
        pdot[wid][lane] = vpack(__fadd_rn(s0, k0), __fadd_rn(s1, k1));
    }

    // --- pre-read conv halos BEFORE xs is overwritten ---
    ull win[13], hal[6];
    #pragma unroll
    for (int i = 0; i < 13; i++) {
        int c = cw0 - 6 + i;
        win[i] = (c >= 0 && c < Cn) ? *(const ull*)(xcol + c * 68) : 0ull;
    }
    #pragma unroll
    for (int i = 0; i < 6; i++) {
        int c = cw0 + CW + i;
        hal[i] = (c < Cn) ? *(const ull*)(xcol + c * 68) : 0ull;
    }
    __syncthreads();

    // --- per-column sigma -> normalized 13-tap kernel (once per column) ---
    if (tid < TT) {
        float s = 0.f;
        #pragma unroll
        for (int w = 0; w < NW1; w++) {
            float lo, hi; vunpack(lo, hi, pdot[w][tid >> 1]);
            s = __fadd_rn(s, (tid & 1) ? hi : lo);
        }
        float w = __fadd_rn(5.2f, __fmul_rn(s, 9.6f));
        w = fminf(fmaxf(w, 0.4f), 10.0f);
        float invw = __fdiv_rn(1.0f, w);

        float kern[13];
        #pragma unroll
        for (int k = 0; k < 13; k++) {
            float q = __fmul_rn((float)(k - 6), invw);
            kern[k] = expf(__fmul_rn(-0.5f, __fmul_rn(q, q)));
        }
        // norm = 2 * sum_{m=0}^{64} exp(-a*(m+0.5)^2), geometric-ratio recurrence
        float q0 = __fmul_rn(0.93023255813953487f, invw);   // (120/129)/w
        float a  = __fmul_rn(0.5f, __fmul_rn(q0, q0));
        float rho  = expf(__fmul_rn(-2.0f, a));
        float term = expf(__fmul_rn(-0.25f, a));
        float ssum = term, qq = rho;
        #pragma unroll 8
        for (int m = 0; m < 64; m++) {
            term = __fmul_rn(term, qq);
            ssum = __fadd_rn(ssum, term);
            qq   = __fmul_rn(qq, rho);
        }
        float invn = __fdiv_rn(1.0f, __fmul_rn(2.0f, ssum));
        #pragma unroll
        for (int k = 0; k < 13; k++)
            kern_s[k * TT + tid] = __fmul_rn(kern[k], invn);
    }
    __syncthreads();

    // --- packed conv (FFMA2), overwrite xs with I = x - relu(x - x_mean) ---
    ull kk[13];
    #pragma unroll
    for (int k = 0; k < 13; k++)
        kk[k] = *(const ull*)(kern_s + k * TT + 2 * lane);

    #pragma unroll
    for (int j = 0; j < CW; j++) {
        ull acc = vmul(win[j % 13], kk[0]);
        #pragma unroll
        for (int i = 1; i < 13; i++)
            acc = vfma(win[(j + i) % 13], kk[i], acc);
        float a0, a1, x0, x1;
        vunpack(a0, a1, acc);
        vunpack(x0, x1, win[(j + 6) % 13]);
        float i0 = __fsub_rn(x0, fmaxf(__fsub_rn(x0, a0), 0.0f));
        float i1 = __fsub_rn(x1, fmaxf(__fsub_rn(x1, a1), 0.0f));
        *(float2*)(xs + (cw0 + j) * 68 + 2 * lane) = make_float2(i0, i1);
        if (j < 21)       win[j % 13] = *(const ull*)(xcol + (cw0 + j + 7) * 68);
        else if (j < 27)  win[j % 13] = hal[j - 21];
    }
    __syncthreads();

    // --- transposed vectorized store: g_IT[(t0+r)*BC + b*224 + 4g..] ---
    float* It = g_IT + (size_t)t0 * BC + b * Cn;
    #pragma unroll
    for (int i = tid; i < 64 * 64; i += 256) {
        int r = i >> 6, g = i & 63;
        if (g < 56) {
            float4 v;
            v.x = xs[(4 * g + 0) * 68 + r];
            v.y = xs[(4 * g + 1) * 68 + r];
            v.z = xs[(4 * g + 2) * 68 + r];
            v.w = xs[(4 * g + 3) * 68 + r];
            *(float4*)(It + (size_t)r * BC + 4 * g) = v;
        }
    }
}

// ---------------------------------------------------------------------------
// Stage 2: LIF scan, one thread per (b,c) sequence, coalesced g_IT reads.
// Hot loop: LDG + FMUL + FSETP + FADD + FSEL + FSUB per step (chain ~13 cyc),
// spikes packed into float4 -> STS.128 every 4 steps; conflict-free
// LDS.128/STG.128 transpose flush every 64 steps. Exact reference op order.
// ---------------------------------------------------------------------------
__global__ void __launch_bounds__(32) agss_stage2(float* __restrict__ out) {
    __shared__ __align__(16) float tile[32][68];   // [lane][t_local], stride 68

    const int lane = threadIdx.x;
    const int seq0 = blockIdx.x * 32;
    const float* base = g_IT + seq0 + lane;
    float* ob = out + (size_t)seq0 * Tn;

    float buf[PF];
    #pragma unroll
    for (int i = 0; i < PF; i++) buf[i] = __ldcs(base + (size_t)i * BC);

    float mem = 0.0f, sp = 0.0f;
    float o0, o1, o2, o3;

    for (int t0 = 0; t0 < Tn; t0 += PF) {
        const float* pre = base + (size_t)(t0 + PF) * BC;
        #pragma unroll
        for (int i = 0; i < PF; i++) {
            float v = buf[i];
            buf[i] = __ldcs(pre + (size_t)i * BC);     // in-bounds (padded)
            // exact reference order: mem = (0.95*mem + v) - sp; spk = mem > 1
            float nm = __fmul_rn(0.95f, mem);
            float q  = __fadd_rn(nm, v);
            mem = __fsub_rn(q, sp);
            sp  = (mem > 1.0f) ? 1.0f : 0.0f;
            if ((i & 3) == 0) o0 = sp;
            if ((i & 3) == 1) o1 = sp;
            if ((i & 3) == 2) o2 = sp;
            if ((i & 3) == 3) {
                o3 = sp;
                *(float4*)&tile[lane][i - 3] = make_float4(o0, o1, o2, o3);
            }
        }
        __syncwarp();
        // flush: 32 rows x 64 t, two rows per pass (lanes 0-15 / 16-31)
        const int rh = lane >> 4;           // 0 or 1
        const int gc = (lane & 15) * 4;     // float4 column within row
        #pragma unroll
        for (int r = 0; r < 32; r += 2) {
            float4 vv = *(const float4*)&tile[r + rh][gc];
            __stcs((float4*)(ob + (size_t)(r + rh) * Tn + t0 + gc), vv);
        }
        __syncwarp();
    }
}

// ---------------------------------------------------------------------------
extern "C" void kernel_launch(void* const* d_in, const int* in_sizes, int n_in,
                              void* d_out, int out_size) {
    const float* inp = (const float*)d_in[0];   // (32,1,224,2048) f32
    const float* lw  = (const float*)d_in[1];   // (1,224) f32
    float* out = (float*)d_out;                 // (32,1,224,2048) f32

    dim3 g1(Tn / TT, Bn);
    agss_stage1<<<g1, 256>>>(inp, lw);
    agss_stage2<<<BC / 32, 32>>>(out);
}

// round 5
// speedup vs baseline: 2.8941x; 1.1268x over previous
#include <cuda_runtime.h>
#include <math.h>

#define Bn 32
#define Cn 224
#define Tn 2048
#define TT 32            // t-columns per stage-1 block
#define NW1 8            // warps per stage-1 block
#define CW 28            // channels per warp (8*28 = 224)
#define BC (Bn * Cn)     // 7168 sequences
#define PF 64            // stage-2 register prefetch depth

// Transposed intermediate I_T[t][seq], padded by PF rows for branch-free prefetch.
__device__ float g_IT[(size_t)(Tn + PF) * BC];

// XOR bank swizzle for the transposed smem tile: keeps both the
// column-write (lanes vary t) and row-read (lanes vary c) conflict-free.
#define SWZ(c, r) (((c) & ~31) | (((c) ^ (r)) & 31))

// ---------------------------------------------------------------------------
// Stage 1: per (b, 32-t-tile), 256 threads = 8 warps x 28 channels.
// Thread (w, lane) owns t-column `lane` for channels [28w, 28w+28).
//   1. slab load x[224][32] -> xs (stride-33 rows, conflict-free)
//   2. per-warp Kahan partial dot -> pdot; warp 0 computes per-column sigma,
//      13-tap kern + geometric-recurrence norm (2 exps) -> kern_s
//   3. sliding-window 13-tap conv (FFMA), I written into XOR-swizzled
//      transposed tile its[t][c] (conflict-free STS)
//   4. flush its -> g_IT[t][seq] (conflict-free LDS, coalesced STG)
// ---------------------------------------------------------------------------
__global__ void __launch_bounds__(256) agss_stage1(const float* __restrict__ x,
                                                   const float* __restrict__ lw) {
    __shared__ float xs[Cn * 33];          // [c][t], stride 33 (conflict-free)
    __shared__ float its[TT * Cn];         // [t][c] XOR-swizzled
    __shared__ float lws[Cn];
    __shared__ float pdot[NW1][32];
    __shared__ float kern_s[13 * TT];

    const int tid  = threadIdx.x;
    const int lane = tid & 31;
    const int wid  = tid >> 5;
    const int b    = blockIdx.y;
    const int t0   = blockIdx.x * TT;
    const int cw0  = wid * CW;

    const float* xb = x + ((size_t)b * Cn) * Tn + t0;

    if (tid < Cn) lws[tid] = lw[tid];

    // slab load: 224 channels x 8 float4 -> scalar STS (bank-clean: 33 ≡ 1 mod 4)
    #pragma unroll
    for (int i = tid; i < Cn * 8; i += 256) {
        int c = i >> 3, j = i & 7;
        float4 v = *(const float4*)(xb + (size_t)c * Tn + 4 * j);
        float* p = xs + c * 33 + 4 * j;
        p[0] = v.x; p[1] = v.y; p[2] = v.z; p[3] = v.w;
    }
    __syncthreads();

    // --- per-warp Kahan partial dot over own 28 channels ---
    {
        float s = 0.f, k = 0.f;
        #pragma unroll
        for (int j = 0; j < CW; j++) {
            int c = cw0 + j;
            float p  = __fmul_rn(xs[c * 33 + lane], lws[c]);
            float y  = __fsub_rn(p, k);
            float t2 = __fadd_rn(s, y);
            k = __fsub_rn(__fsub_rn(t2, s), y);
            s = t2;
        }
        pdot[wid][lane] = __fadd_rn(s, k);
    }
    __syncthreads();

    // --- warp 0: per-column sigma -> normalized 13-tap kernel ---
    if (tid < TT) {
        float s = pdot[0][tid];
        #pragma unroll
        for (int w = 1; w < NW1; w++) s = __fadd_rn(s, pdot[w][tid]);
        float w = __fadd_rn(5.2f, __fmul_rn(s, 9.6f));
        w = fminf(fmaxf(w, 0.4f), 10.0f);
        float invw = __fdiv_rn(1.0f, w);

        float kern[13];
        #pragma unroll
        for (int k = 0; k < 13; k++) {
            float q = __fmul_rn((float)(k - 6), invw);
            kern[k] = expf(__fmul_rn(-0.5f, __fmul_rn(q, q)));
        }
        // norm = 2 * sum_{m=0}^{64} exp(-a*(m+0.5)^2) via geometric recurrence
        float q0 = __fmul_rn(0.93023255813953487f, invw);   // (120/129)/w
        float a  = __fmul_rn(0.5f, __fmul_rn(q0, q0));
        float rho  = expf(__fmul_rn(-2.0f, a));
        float term = expf(__fmul_rn(-0.25f, a));
        float ssum = term, qq = rho;
        #pragma unroll 8
        for (int m = 0; m < 64; m++) {
            term = __fmul_rn(term, qq);
            ssum = __fadd_rn(ssum, term);
            qq   = __fmul_rn(qq, rho);
        }
        float invn = __fdiv_rn(1.0f, __fmul_rn(2.0f, ssum));
        #pragma unroll
        for (int k = 0; k < 13; k++)
            kern_s[k * TT + tid] = __fmul_rn(kern[k], invn);
    }
    __syncthreads();

    // --- sliding-window conv; xs is read-only, output to swizzled its ---
    float kk[13];
    #pragma unroll
    for (int k = 0; k < 13; k++) kk[k] = kern_s[k * TT + lane];

    float win[13];
    #pragma unroll
    for (int i = 0; i < 13; i++) {
        int c = cw0 - 6 + i;
        win[i] = (c >= 0 && c < Cn) ? xs[c * 33 + lane] : 0.0f;
    }

    #pragma unroll
    for (int j = 0; j < CW; j++) {
        float acc = __fmul_rn(win[j % 13], kk[0]);
        #pragma unroll
        for (int i = 1; i < 13; i++)
            acc = fmaf(win[(j + i) % 13], kk[i], acc);
        float xc = win[(j + 6) % 13];
        float I  = __fsub_rn(xc, fmaxf(__fsub_rn(xc, acc), 0.0f));
        int c = cw0 + j;
        its[lane * Cn + SWZ(c, lane)] = I;          // banks (c^lane)&31: clean
        int cn = c + 7;
        win[j % 13] = (cn < Cn) ? xs[cn * 33 + lane] : 0.0f;
    }
    __syncthreads();

    // --- flush: g_IT[(t0+r)*BC + b*224 + cc], coalesced STG, clean LDS ---
    float* It = g_IT + (size_t)t0 * BC + b * Cn;
    if (tid < Cn) {
        #pragma unroll
        for (int r = 0; r < TT; r++)
            It[(size_t)r * BC + tid] = its[r * Cn + SWZ(tid, r)];
    }
}

// ---------------------------------------------------------------------------
// Stage 2: LIF scan, one thread per (b,c) sequence, coalesced g_IT reads.
// Speculative update: both reset candidates computed, FSEL'd by the PREVIOUS
// step's predicate -> FSETP leaves the loop-carried cycle (21 -> ~17 cyc).
// Bit-exact vs reference (FSUB by 0.0/1.0 == candidate select).
// ---------------------------------------------------------------------------
__global__ void __launch_bounds__(32) agss_stage2(float* __restrict__ out) {
    __shared__ __align__(16) float tile[32][68];   // [lane][t_local]

    const int lane = threadIdx.x;
    const int seq0 = blockIdx.x * 32;
    const float* base = g_IT + seq0 + lane;
    float* ob = out + (size_t)seq0 * Tn;

    float buf[PF];
    #pragma unroll
    for (int i = 0; i < PF; i++) buf[i] = __ldcs(base + (size_t)i * BC);

    float mem = 0.0f;
    bool  P   = false;                 // P = (mem > 1) = spk_{t-1} = reset_t
    float o0, o1, o2, o3;

    for (int t0 = 0; t0 < Tn; t0 += PF) {
        const float* pre = base + (size_t)(t0 + PF) * BC;
        #pragma unroll
        for (int i = 0; i < PF; i++) {
            float v = buf[i];
            buf[i] = __ldcs(pre + (size_t)i * BC);       // in-bounds (padded)
            float A  = __fadd_rn(__fmul_rn(0.95f, mem), v);
            float A1 = __fsub_rn(A, 1.0f);
            mem = P ? A1 : A;          // == FSUB(A, reset), bit-exact
            P = (mem > 1.0f);
            float sp = P ? 1.0f : 0.0f;
            if ((i & 3) == 0) o0 = sp;
            if ((i & 3) == 1) o1 = sp;
            if ((i & 3) == 2) o2 = sp;
            if ((i & 3) == 3) {
                o3 = sp;
                *(float4*)&tile[lane][i - 3] = make_float4(o0, o1, o2, o3);
            }
        }
        __syncwarp();
        const int rh = lane >> 4;
        const int gc = (lane & 15) * 4;
        #pragma unroll
        for (int r = 0; r < 32; r += 2) {
            float4 vv = *(const float4*)&tile[r + rh][gc];
            __stcs((float4*)(ob + (size_t)(r + rh) * Tn + t0 + gc), vv);
        }
        __syncwarp();
    }
}

// ---------------------------------------------------------------------------
extern "C" void kernel_launch(void* const* d_in, const int* in_sizes, int n_in,
                              void* d_out, int out_size) {
    const float* inp = (const float*)d_in[0];   // (32,1,224,2048) f32
    const float* lw  = (const float*)d_in[1];   // (1,224) f32
    float* out = (float*)d_out;                 // (32,1,224,2048) f32

    dim3 g1(Tn / TT, Bn);
    agss_stage1<<<g1, 256>>>(inp, lw);
    agss_stage2<<<BC / 32, 32>>>(out);
}

// round 6
// speedup vs baseline: 3.2054x; 1.1075x over previous
#include <cuda_runtime.h>
#include <math.h>

#define Bn 32
#define Cn 224
#define Tn 2048
#define TT 32            // t-columns per stage-1 block
#define NW1 8            // warps per stage-1 block
#define CW 28            // channels per warp (8*28 = 224)
#define BC (Bn * Cn)     // 7168 sequences
#define PF 64            // stage-2 register prefetch depth

// Transposed intermediate I_T[t][seq], padded by PF rows for branch-free prefetch.
__device__ float g_IT[(size_t)(Tn + PF) * BC];

// XOR bank swizzle for the transposed smem tile: keeps both the
// column-write (lanes vary t) and row-read (lanes vary c) conflict-free.
#define SWZ(c, r) (((c) & ~31) | (((c) ^ (r)) & 31))

// ---------------------------------------------------------------------------
// Stage 1 (unchanged from R5 — measured 35.7us): per (b, 32-t-tile),
// 256 threads = 8 warps x 28 channels.
// ---------------------------------------------------------------------------
__global__ void __launch_bounds__(256) agss_stage1(const float* __restrict__ x,
                                                   const float* __restrict__ lw) {
    __shared__ float xs[Cn * 33];          // [c][t], stride 33 (conflict-free)
    __shared__ float its[TT * Cn];         // [t][c] XOR-swizzled
    __shared__ float lws[Cn];
    __shared__ float pdot[NW1][32];
    __shared__ float kern_s[13 * TT];

    const int tid  = threadIdx.x;
    const int lane = tid & 31;
    const int wid  = tid >> 5;
    const int b    = blockIdx.y;
    const int t0   = blockIdx.x * TT;
    const int cw0  = wid * CW;

    const float* xb = x + ((size_t)b * Cn) * Tn + t0;

    if (tid < Cn) lws[tid] = lw[tid];

    // slab load: 224 channels x 8 float4 -> scalar STS (bank-clean)
    #pragma unroll
    for (int i = tid; i < Cn * 8; i += 256) {
        int c = i >> 3, j = i & 7;
        float4 v = *(const float4*)(xb + (size_t)c * Tn + 4 * j);
        float* p = xs + c * 33 + 4 * j;
        p[0] = v.x; p[1] = v.y; p[2] = v.z; p[3] = v.w;
    }
    __syncthreads();

    // --- per-warp Kahan partial dot over own 28 channels ---
    {
        float s = 0.f, k = 0.f;
        #pragma unroll
        for (int j = 0; j < CW; j++) {
            int c = cw0 + j;
            float p  = __fmul_rn(xs[c * 33 + lane], lws[c]);
            float y  = __fsub_rn(p, k);
            float t2 = __fadd_rn(s, y);
            k = __fsub_rn(__fsub_rn(t2, s), y);
            s = t2;
        }
        pdot[wid][lane] = __fadd_rn(s, k);
    }
    __syncthreads();

    // --- warp 0: per-column sigma -> normalized 13-tap kernel ---
    if (tid < TT) {
        float s = pdot[0][tid];
        #pragma unroll
        for (int w = 1; w < NW1; w++) s = __fadd_rn(s, pdot[w][tid]);
        float w = __fadd_rn(5.2f, __fmul_rn(s, 9.6f));
        w = fminf(fmaxf(w, 0.4f), 10.0f);
        float invw = __fdiv_rn(1.0f, w);

        float kern[13];
        #pragma unroll
        for (int k = 0; k < 13; k++) {
            float q = __fmul_rn((float)(k - 6), invw);
            kern[k] = expf(__fmul_rn(-0.5f, __fmul_rn(q, q)));
        }
        // norm = 2 * sum_{m=0}^{64} exp(-a*(m+0.5)^2) via geometric recurrence
        float q0 = __fmul_rn(0.93023255813953487f, invw);   // (120/129)/w
        float a  = __fmul_rn(0.5f, __fmul_rn(q0, q0));
        float rho  = expf(__fmul_rn(-2.0f, a));
        float term = expf(__fmul_rn(-0.25f, a));
        float ssum = term, qq = rho;
        #pragma unroll 8
        for (int m = 0; m < 64; m++) {
            term = __fmul_rn(term, qq);
            ssum = __fadd_rn(ssum, term);
            qq   = __fmul_rn(qq, rho);
        }
        float invn = __fdiv_rn(1.0f, __fmul_rn(2.0f, ssum));
        #pragma unroll
        for (int k = 0; k < 13; k++)
            kern_s[k * TT + tid] = __fmul_rn(kern[k], invn);
    }
    __syncthreads();

    // --- sliding-window conv; xs is read-only, output to swizzled its ---
    float kk[13];
    #pragma unroll
    for (int k = 0; k < 13; k++) kk[k] = kern_s[k * TT + lane];

    float win[13];
    #pragma unroll
    for (int i = 0; i < 13; i++) {
        int c = cw0 - 6 + i;
        win[i] = (c >= 0 && c < Cn) ? xs[c * 33 + lane] : 0.0f;
    }

    #pragma unroll
    for (int j = 0; j < CW; j++) {
        float acc = __fmul_rn(win[j % 13], kk[0]);
        #pragma unroll
        for (int i = 1; i < 13; i++)
            acc = fmaf(win[(j + i) % 13], kk[i], acc);
        float xc = win[(j + 6) % 13];
        float I  = __fsub_rn(xc, fmaxf(__fsub_rn(xc, acc), 0.0f));
        int c = cw0 + j;
        its[lane * Cn + SWZ(c, lane)] = I;          // banks (c^lane)&31: clean
        int cn = c + 7;
        win[j % 13] = (cn < Cn) ? xs[cn * 33 + lane] : 0.0f;
    }
    __syncthreads();

    // --- flush: g_IT[(t0+r)*BC + b*224 + cc], coalesced STG, clean LDS ---
    float* It = g_IT + (size_t)t0 * BC + b * Cn;
    if (tid < Cn) {
        #pragma unroll
        for (int r = 0; r < TT; r++)
            It[(size_t)r * BC + tid] = its[r * Cn + SWZ(tid, r)];
    }
}

// ---------------------------------------------------------------------------
// Stage 2: LIF scan, one thread per (b,c) sequence, coalesced g_IT reads.
// Spike materialized by a single FSET (set.gt.f32.f32 -> 1.0f/0.0f), taking
// the 13-cycle FSETP predicate latency OFF the loop-carried chain:
//   chain: mem -> FSET(~4) || FMUL->FADD -> FSUB   ~= 12 cyc/step.
// Semantics identical to reference: mem = (0.95*mem + I) - spk_prev,
// spk = (mem > 1) as float.
// ---------------------------------------------------------------------------
__global__ void __launch_bounds__(32) agss_stage2(float* __restrict__ out) {
    __shared__ __align__(16) float tile[32][68];   // [lane][t_local]

    const int lane = threadIdx.x;
    const int seq0 = blockIdx.x * 32;
    const float* base = g_IT + seq0 + lane;
    float* ob = out + (size_t)seq0 * Tn;

    float buf[PF];
    #pragma unroll
    for (int i = 0; i < PF; i++) buf[i] = __ldcs(base + (size_t)i * BC);

    float mem = 0.0f, spf = 0.0f;      // spf = spike_{t-1} = reset_t (float)
    float o0, o1, o2, o3;

    for (int t0 = 0; t0 < Tn; t0 += PF) {
        const float* pre = base + (size_t)(t0 + PF) * BC;
        #pragma unroll
        for (int i = 0; i < PF; i++) {
            float v = buf[i];
            buf[i] = __ldcs(pre + (size_t)i * BC);       // in-bounds (padded)
            // exact reference order: mem = (0.95*mem + v) - spf
            float q = __fadd_rn(__fmul_rn(0.95f, mem), v);
            mem = __fsub_rn(q, spf);
            // spf = (mem > 1.0f) ? 1.0f : 0.0f  -- single FSET, no predicate
            asm("set.gt.f32.f32 %0, %1, %2;" : "=f"(spf) : "f"(mem), "f"(1.0f));
            if ((i & 3) == 0) o0 = spf;
            if ((i & 3) == 1) o1 = spf;
            if ((i & 3) == 2) o2 = spf;
            if ((i & 3) == 3) {
                o3 = spf;
                *(float4*)&tile[lane][i - 3] = make_float4(o0, o1, o2, o3);
            }
        }
        __syncwarp();
        const int rh = lane >> 4;
        const int gc = (lane & 15) * 4;
        #pragma unroll
        for (int r = 0; r < 32; r += 2) {
            float4 vv = *(const float4*)&tile[r + rh][gc];
            __stcs((float4*)(ob + (size_t)(r + rh) * Tn + t0 + gc), vv);
        }
        __syncwarp();
    }
}

// ---------------------------------------------------------------------------
extern "C" void kernel_launch(void* const* d_in, const int* in_sizes, int n_in,
                              void* d_out, int out_size) {
    const float* inp = (const float*)d_in[0];   // (32,1,224,2048) f32
    const float* lw  = (const float*)d_in[1];   // (1,224) f32
    float* out = (float*)d_out;                 // (32,1,224,2048) f32

    dim3 g1(Tn / TT, Bn);
    agss_stage1<<<g1, 256>>>(inp, lw);
    agss_stage2<<<BC / 32, 32>>>(out);
}

// round 8
// speedup vs baseline: 3.4561x; 1.0782x over previous
#include <cuda_runtime.h>
#include <cstdint>
#include <math.h>

#define Bn 32
#define Cn 224
#define Tn 2048
#define TT 32            // t-columns per stage-1 block
#define NW1 8            // warps per stage-1 block
#define CW 28            // channels per warp (8*28 = 224)
#define BC (Bn * Cn)     // 7168 sequences
#define PAD 128          // g_IT row padding (stage-2 prefetch distance 2 chunks)

// Transposed intermediate I_T[t][seq], padded so chunk prefetch never runs OOB.
__device__ float g_IT[(size_t)(Tn + PAD) * BC];

// XOR bank swizzle for the transposed smem tile (stage 1).
#define SWZ(c, r) (((c) & ~31) | (((c) ^ (r)) & 31))

#define CP_ASYNC16(dst, src) \
    asm volatile("cp.async.cg.shared.global [%0], [%1], 16;" :: "r"(dst), "l"(src) : "memory")
#define CP_COMMIT() asm volatile("cp.async.commit_group;" ::: "memory")
#define CP_WAIT1()  asm volatile("cp.async.wait_group 1;" ::: "memory")

// ---------------------------------------------------------------------------
// Stage 1 (unchanged from R5/R6 — measured ~35.7us).
// ---------------------------------------------------------------------------
__global__ void __launch_bounds__(256) agss_stage1(const float* __restrict__ x,
                                                   const float* __restrict__ lw) {
    __shared__ float xs[Cn * 33];          // [c][t], stride 33 (conflict-free)
    __shared__ float its[TT * Cn];         // [t][c] XOR-swizzled
    __shared__ float lws[Cn];
    __shared__ float pdot[NW1][32];
    __shared__ float kern_s[13 * TT];

    const int tid  = threadIdx.x;
    const int lane = tid & 31;
    const int wid  = tid >> 5;
    const int b    = blockIdx.y;
    const int t0   = blockIdx.x * TT;
    const int cw0  = wid * CW;

    const float* xb = x + ((size_t)b * Cn) * Tn + t0;

    if (tid < Cn) lws[tid] = lw[tid];

    #pragma unroll
    for (int i = tid; i < Cn * 8; i += 256) {
        int c = i >> 3, j = i & 7;
        float4 v = *(const float4*)(xb + (size_t)c * Tn + 4 * j);
        float* p = xs + c * 33 + 4 * j;
        p[0] = v.x; p[1] = v.y; p[2] = v.z; p[3] = v.w;
    }
    __syncthreads();

    // --- per-warp Kahan partial dot over own 28 channels ---
    {
        float s = 0.f, k = 0.f;
        #pragma unroll
        for (int j = 0; j < CW; j++) {
            int c = cw0 + j;
            float p  = __fmul_rn(xs[c * 33 + lane], lws[c]);
            float y  = __fsub_rn(p, k);
            float t2 = __fadd_rn(s, y);
            k = __fsub_rn(__fsub_rn(t2, s), y);
            s = t2;
        }
        pdot[wid][lane] = __fadd_rn(s, k);
    }
    __syncthreads();

    // --- warp 0: per-column sigma -> normalized 13-tap kernel ---
    if (tid < TT) {
        float s = pdot[0][tid];
        #pragma unroll
        for (int w = 1; w < NW1; w++) s = __fadd_rn(s, pdot[w][tid]);
        float w = __fadd_rn(5.2f, __fmul_rn(s, 9.6f));
        w = fminf(fmaxf(w, 0.4f), 10.0f);
        float invw = __fdiv_rn(1.0f, w);

        float kern[13];
        #pragma unroll
        for (int k = 0; k < 13; k++) {
            float q = __fmul_rn((float)(k - 6), invw);
            kern[k] = expf(__fmul_rn(-0.5f, __fmul_rn(q, q)));
        }
        float q0 = __fmul_rn(0.93023255813953487f, invw);   // (120/129)/w
        float a  = __fmul_rn(0.5f, __fmul_rn(q0, q0));
        float rho  = expf(__fmul_rn(-2.0f, a));
        float term = expf(__fmul_rn(-0.25f, a));
        float ssum = term, qq = rho;
        #pragma unroll 8
        for (int m = 0; m < 64; m++) {
            term = __fmul_rn(term, qq);
            ssum = __fadd_rn(ssum, term);
            qq   = __fmul_rn(qq, rho);
        }
        float invn = __fdiv_rn(1.0f, __fmul_rn(2.0f, ssum));
        #pragma unroll
        for (int k = 0; k < 13; k++)
            kern_s[k * TT + tid] = __fmul_rn(kern[k], invn);
    }
    __syncthreads();

    // --- sliding-window conv; xs read-only, output to swizzled its ---
    float kk[13];
    #pragma unroll
    for (int k = 0; k < 13; k++) kk[k] = kern_s[k * TT + lane];

    float win[13];
    #pragma unroll
    for (int i = 0; i < 13; i++) {
        int c = cw0 - 6 + i;
        win[i] = (c >= 0 && c < Cn) ? xs[c * 33 + lane] : 0.0f;
    }

    #pragma unroll
    for (int j = 0; j < CW; j++) {
        float acc = __fmul_rn(win[j % 13], kk[0]);
        #pragma unroll
        for (int i = 1; i < 13; i++)
            acc = fmaf(win[(j + i) % 13], kk[i], acc);
        float xc = win[(j + 6) % 13];
        float I  = __fsub_rn(xc, fmaxf(__fsub_rn(xc, acc), 0.0f));
        int c = cw0 + j;
        its[lane * Cn + SWZ(c, lane)] = I;
        int cn = c + 7;
        win[j % 13] = (cn < Cn) ? xs[cn * 33 + lane] : 0.0f;
    }
    __syncthreads();

    // --- flush: coalesced STG, conflict-free LDS ---
    float* It = g_IT + (size_t)t0 * BC + b * Cn;
    if (tid < Cn) {
        #pragma unroll
        for (int r = 0; r < TT; r++)
            It[(size_t)r * BC + tid] = its[r * Cn + SWZ(tid, r)];
    }
}

// ---------------------------------------------------------------------------
// Stage 2: LIF scan, one warp per 32 sequences. Input streamed via cp.async
// into a 3-stage smem ring (prefetch distance 2 chunks => one wait_group per
// 64 steps, no register-scoreboard aliasing). Hot chain:
//   mem -> FMUL(imm) -> FADD -> FSUB, FSET off-chain  ~= 12-16 cyc/step.
// Exact reference op order; spike = set.gt.f32 (1.0f/0.0f).
// ---------------------------------------------------------------------------
__global__ void __launch_bounds__(32) agss_stage2(float* __restrict__ out) {
    __shared__ __align__(16) float stile[3][64 * 32];   // input ring [stage][t][lane]
    __shared__ __align__(16) float otile[32][68];       // output staging

    const int lane = threadIdx.x;
    const int seq0 = blockIdx.x * 32;
    float* ob = out + (size_t)seq0 * Tn;

    // cooperative cp.async lane mapping: lane covers row (lane>>3), 16B col chunk
    const int rsub = lane >> 3;            // 0..3
    const int csub = (lane & 7) * 4;       // 0..28
    unsigned int sb = (unsigned int)__cvta_generic_to_shared(&stile[0][0]);
    const unsigned int dlane = sb + (unsigned int)((rsub * 32 + csub) * 4);
    const float* glane = g_IT + seq0 + (size_t)rsub * BC + csub;

    // prefetch chunks 0 and 1 into stages 0, 1
    #pragma unroll
    for (int k = 0; k < 2; k++) {
        unsigned int d = dlane + (unsigned int)(k * 64 * 32 * 4);
        const float* g = glane + (size_t)(k * 64) * BC;
        #pragma unroll
        for (int j = 0; j < 16; j++)
            CP_ASYNC16(d + (unsigned int)(j * 4 * 32 * 4), g + (size_t)(4 * j) * BC);
        CP_COMMIT();
    }

    float mem = 0.0f, spf = 0.0f;
    float o0, o1, o2, o3;

    #pragma unroll 1
    for (int k = 0; k < Tn / 64; k++) {
        CP_WAIT1();                       // chunk k complete (<=1 group pending)
        __syncwarp();

        const float* st = &stile[0][0] + (k % 3) * (64 * 32) + lane;
        #pragma unroll
        for (int i = 0; i < 64; i++) {
            float v = st[i * 32];
            // exact reference order: mem = (0.95*mem + v) - spk_prev
            float q = __fadd_rn(__fmul_rn(0.95f, mem), v);
            mem = __fsub_rn(q, spf);
            asm("set.gt.f32.f32 %0, %1, %2;" : "=f"(spf) : "f"(mem), "f"(1.0f));
            if ((i & 3) == 0) o0 = spf;
            if ((i & 3) == 1) o1 = spf;
            if ((i & 3) == 2) o2 = spf;
            if ((i & 3) == 3) {
                o3 = spf;
                *(float4*)&otile[lane][i - 3] = make_float4(o0, o1, o2, o3);
            }
        }

        // prefetch chunk k+2 into stage (k+2)%3 (never the stage being read)
        {
            unsigned int d = dlane + (unsigned int)(((k + 2) % 3) * 64 * 32 * 4);
            const float* g = glane + (size_t)((k + 2) * 64) * BC;  // padded OOB-safe
            #pragma unroll
            for (int j = 0; j < 16; j++)
                CP_ASYNC16(d + (unsigned int)(j * 4 * 32 * 4), g + (size_t)(4 * j) * BC);
            CP_COMMIT();
        }

        __syncwarp();
        const int rh = lane >> 4;
        const int gc = (lane & 15) * 4;
        const int t0 = k * 64;
        #pragma unroll
        for (int r = 0; r < 32; r += 2) {
            float4 vv = *(const float4*)&otile[r + rh][gc];
            __stcs((float4*)(ob + (size_t)(r + rh) * Tn + t0 + gc), vv);
        }
        __syncwarp();
    }
}

// ---------------------------------------------------------------------------
extern "C" void kernel_launch(void* const* d_in, const int* in_sizes, int n_in,
                              void* d_out, int out_size) {
    const float* inp = (const float*)d_in[0];   // (32,1,224,2048) f32
    const float* lw  = (const float*)d_in[1];   // (1,224) f32
    float* out = (float*)d_out;                 // (32,1,224,2048) f32

    dim3 g1(Tn / TT, Bn);
    agss_stage1<<<g1, 256>>>(inp, lw);
    agss_stage2<<<BC / 32, 32>>>(out);
}